// round 3
// baseline (speedup 1.0000x reference)
#include <cuda_runtime.h>
#include <math.h>

// ---------------- problem constants ----------------
constexpr int CB   = 256;   // batch
constexpr int CTXD = 512;
constexpr int DOF  = 6;
constexpr int WSZ  = 300;
constexpr int PGD  = 256;
constexpr int PWD  = 512;
constexpr int HGD  = 256;
constexpr int HWD  = 512;
constexpr int ZD   = 306;   // DOF + WSZ
constexpr int NSTEP = 19;   // max_segments - 1

// ---------------- scratch layout (single __device__ array, no allocs) ----------
constexpr size_t OFF_TMPW = 0;
constexpr size_t SZ_TMPW  = (size_t)CB * PWD * ZD;          // 40,108,032
constexpr size_t OFF_TMPG = OFF_TMPW + SZ_TMPW;
constexpr size_t SZ_TMPG  = (size_t)CB * PGD * DOF;
constexpr size_t OFF_CTXT = OFF_TMPG + SZ_TMPG;             // ctx transposed [i][b]
constexpr size_t OFF_PG   = OFF_CTXT + (size_t)CTXD * CB;
constexpr size_t OFF_PW   = OFF_PG + (size_t)CB * DOF;
constexpr size_t OFF_XPRE = OFF_PW + (size_t)CB * WSZ;
constexpr size_t OFF_YPRE = OFF_XPRE + (size_t)CB * PGD;
constexpr size_t OFF_X    = OFF_YPRE + (size_t)CB * PWD;
constexpr size_t OFF_Y    = OFF_X + (size_t)CB * PGD;
constexpr size_t OFF_GG   = OFF_Y + (size_t)CB * PWD;       // gates g: 256x1024
constexpr size_t OFF_GW   = OFF_GG + (size_t)CB * 4 * HGD;  // gates w: 256x2048
constexpr size_t OFF_GH   = OFF_GW + (size_t)CB * 4 * HWD;  // 2 x 256 x 256
constexpr size_t OFF_GC   = OFF_GH + (size_t)2 * CB * HGD;
constexpr size_t OFF_WH   = OFF_GC + (size_t)2 * CB * HGD;  // 2 x 256 x 512
constexpr size_t OFF_WC   = OFF_WH + (size_t)2 * CB * HWD;
constexpr size_t SZ_TOTAL = OFF_WC + (size_t)2 * CB * HWD;

__device__ float g_buf[SZ_TOTAL];

__device__ __forceinline__ float sigm(float x) { return 1.0f / (1.0f + expf(-x)); }

// ---------------- transpose ctx -> ctxT[i][b] ----------------
__global__ void k_transpose_ctx(const float* __restrict__ ctx) {
    int idx = blockIdx.x * 256 + threadIdx.x;           // 131072 elems
    if (idx >= CB * CTXD) return;
    int b = idx / CTXD, i = idx % CTXD;
    g_buf[OFF_CTXT + (size_t)i * CB + b] = ctx[idx];
}

// ---------------- tmp_g[b][o][j] = sum_i ctx[b,i] * bg_W[o,i,j] ----------------
__global__ __launch_bounds__(256) void k_tmpg(const float* __restrict__ bgW) {
    int o = blockIdx.x;      // 0..255
    int b = threadIdx.x;     // 0..255
    float acc[DOF];
#pragma unroll
    for (int j = 0; j < DOF; ++j) acc[j] = 0.f;
    const float* ctxT = &g_buf[OFF_CTXT];
    for (int i = 0; i < CTXD; ++i) {
        float c = ctxT[(size_t)i * CB + b];
        const float* w = &bgW[((size_t)o * CTXD + i) * DOF];
#pragma unroll
        for (int j = 0; j < DOF; ++j) acc[j] = fmaf(c, w[j], acc[j]);
    }
    float* out = &g_buf[OFF_TMPG + ((size_t)b * PGD + o) * DOF];
#pragma unroll
    for (int j = 0; j < DOF; ++j) out[j] = acc[j];
}

// ---------------- tmp_w precompute: per-o GEMM  C_o[b][j] = ctx @ bw_W[o] ------
// grid (5 n-tiles, 4 m-tiles, 512 o), block 256, 64x64x16 tile, 4x4 microtile
__global__ __launch_bounds__(256) void k_tmpw(const float* __restrict__ ctx,
                                              const float* __restrict__ bwW) {
    int o  = blockIdx.z;
    int n0 = blockIdx.x * 64;
    int m0 = blockIdx.y * 64;
    const float* Bo = bwW + (size_t)o * CTXD * ZD;

    __shared__ float As[16][64];
    __shared__ float Bs[16][64];
    int tid = threadIdx.x;
    int lm = tid >> 2, lk4 = (tid & 3) * 4;
    int tx = tid & 15, ty = tid >> 4;

    float acc[4][4];
#pragma unroll
    for (int i = 0; i < 4; ++i)
#pragma unroll
        for (int j = 0; j < 4; ++j) acc[i][j] = 0.f;

    for (int k0 = 0; k0 < CTXD; k0 += 16) {
        float4 av = *(const float4*)&ctx[(size_t)(m0 + lm) * CTXD + k0 + lk4];
        As[lk4 + 0][lm] = av.x; As[lk4 + 1][lm] = av.y;
        As[lk4 + 2][lm] = av.z; As[lk4 + 3][lm] = av.w;
#pragma unroll
        for (int r = 0; r < 4; ++r) {
            int k = (tid >> 6) + r * 4;
            int n = tid & 63;
            float v = 0.f;
            if (n0 + n < ZD) v = Bo[(size_t)(k0 + k) * ZD + n0 + n];
            Bs[k][n] = v;
        }
        __syncthreads();
#pragma unroll
        for (int kk = 0; kk < 16; ++kk) {
            float4 a = *(const float4*)&As[kk][ty * 4];
            float4 bq = *(const float4*)&Bs[kk][tx * 4];
            float a_[4] = {a.x, a.y, a.z, a.w};
            float b_[4] = {bq.x, bq.y, bq.z, bq.w};
#pragma unroll
            for (int i = 0; i < 4; ++i)
#pragma unroll
                for (int j = 0; j < 4; ++j) acc[i][j] = fmaf(a_[i], b_[j], acc[i][j]);
        }
        __syncthreads();
    }
#pragma unroll
    for (int i = 0; i < 4; ++i) {
        int b = m0 + ty * 4 + i;
#pragma unroll
        for (int j = 0; j < 4; ++j) {
            int n = n0 + tx * 4 + j;
            if (n < ZD)
                g_buf[OFF_TMPW + ((size_t)b * PWD + o) * ZD + n] = acc[i][j];
        }
    }
}

// ---------------- init: zero states, seed outputs and pg/pw -------------------
__global__ void k_init(const float* __restrict__ goal0, const float* __restrict__ w0,
                       float* __restrict__ out) {
    int idx = blockIdx.x * 256 + threadIdx.x;
    const int R0 = 2 * CB * HGD;            // gh, gc
    const int R1 = 2 * CB * HWD;            // wh, wc
    const int R2 = CB * DOF;
    const int R3 = CB * WSZ;
    if (idx < R0) {
        g_buf[OFF_GH + idx] = 0.f;
        g_buf[OFF_GC + idx] = 0.f;
    } else if (idx < R0 + R1) {
        int j = idx - R0;
        g_buf[OFF_WH + j] = 0.f;
        g_buf[OFF_WC + j] = 0.f;
    } else if (idx < R0 + R1 + R2) {
        int j = idx - R0 - R1;
        float v = goal0[j];
        g_buf[OFF_PG + j] = v;
        out[(size_t)(j / DOF) * 20 * DOF + (j % DOF)] = v;   // goals[:,0,:]
    } else if (idx < R0 + R1 + R2 + R3) {
        int j = idx - R0 - R1 - R2;
        float v = w0[j];
        g_buf[OFF_PW + j] = v;
        out[(size_t)CB * 20 * DOF + (size_t)(j / WSZ) * 20 * WSZ + (j % WSZ)] = v;
    }
}

// ---------------- per-step bilinear: ypre (tmp_w matvec) + xpre ---------------
// grid (256 b, 9), block 256.  tile 0..7: 64 o's of ypre; tile 8: xpre (256 o)
__global__ __launch_bounds__(256) void k_bilinear(const float* __restrict__ bg_b,
                                                  const float* __restrict__ bw_b) {
    int b = blockIdx.x;
    int tile = blockIdx.y;
    __shared__ float zs[ZD];
    int tid = threadIdx.x;
    for (int j = tid; j < ZD; j += 256)
        zs[j] = (j < DOF) ? g_buf[OFF_PG + b * DOF + j]
                          : g_buf[OFF_PW + b * WSZ + (j - DOF)];
    __syncthreads();

    if (tile == 8) {
        int o = tid;
        const float* tg = &g_buf[OFF_TMPG + ((size_t)b * PGD + o) * DOF];
        float acc = bg_b[o];
#pragma unroll
        for (int j = 0; j < DOF; ++j) acc = fmaf(tg[j], zs[j], acc);
        g_buf[OFF_XPRE + b * PGD + o] = acc;
        return;
    }
    int w = tid >> 5, lane = tid & 31;
#pragma unroll
    for (int r = 0; r < 8; ++r) {
        int o = tile * 64 + w * 8 + r;
        const float* tw = &g_buf[OFF_TMPW + ((size_t)b * PWD + o) * ZD];
        float acc = 0.f;
        for (int j = lane; j < ZD; j += 32) acc = fmaf(tw[j], zs[j], acc);
#pragma unroll
        for (int s = 16; s > 0; s >>= 1) acc += __shfl_xor_sync(0xffffffffu, acc, s);
        if (lane == 0) g_buf[OFF_YPRE + b * PWD + o] = acc + bw_b[o];
    }
}

// ---------------- generic dual GEMM-NT:  C = act(A1@B1^T + A2@B2^T + biases) --
struct Prob {
    const float *A1, *B1; int K1;
    const float *A2, *B2; int K2;       // A2 == nullptr -> skip
    const float *bias1, *bias2;         // nullable
    float *C;  int ldc;
    float *C2; int ldc2;                // nullable second destination
    int M, N;
    int act;                            // 1 = tanh
};

__global__ __launch_bounds__(256) void k_gemm_dual(Prob p0, Prob p1) {
    Prob p = (blockIdx.z == 0) ? p0 : p1;
    int n0 = blockIdx.x * 64, m0 = blockIdx.y * 64;
    if (n0 >= p.N || m0 >= p.M) return;

    __shared__ float As[16][64];
    __shared__ float Bs[16][64];
    int tid = threadIdx.x;
    int lm = tid >> 2, lk4 = (tid & 3) * 4;
    int tx = tid & 15, ty = tid >> 4;

    float acc[4][4];
#pragma unroll
    for (int i = 0; i < 4; ++i)
#pragma unroll
        for (int j = 0; j < 4; ++j) acc[i][j] = 0.f;

    for (int phase = 0; phase < 2; ++phase) {
        const float* A = phase ? p.A2 : p.A1;
        const float* Bm = phase ? p.B2 : p.B1;
        int K = phase ? p.K2 : p.K1;
        if (A == nullptr) continue;
        for (int k0 = 0; k0 < K; k0 += 16) {
            float4 av = *(const float4*)&A[(size_t)(m0 + lm) * K + k0 + lk4];
            As[lk4 + 0][lm] = av.x; As[lk4 + 1][lm] = av.y;
            As[lk4 + 2][lm] = av.z; As[lk4 + 3][lm] = av.w;
            float4 bv = make_float4(0.f, 0.f, 0.f, 0.f);
            if (n0 + lm < p.N) bv = *(const float4*)&Bm[(size_t)(n0 + lm) * K + k0 + lk4];
            Bs[lk4 + 0][lm] = bv.x; Bs[lk4 + 1][lm] = bv.y;
            Bs[lk4 + 2][lm] = bv.z; Bs[lk4 + 3][lm] = bv.w;
            __syncthreads();
#pragma unroll
            for (int kk = 0; kk < 16; ++kk) {
                float4 a = *(const float4*)&As[kk][ty * 4];
                float4 bq = *(const float4*)&Bs[kk][tx * 4];
                float a_[4] = {a.x, a.y, a.z, a.w};
                float b_[4] = {bq.x, bq.y, bq.z, bq.w};
#pragma unroll
                for (int i = 0; i < 4; ++i)
#pragma unroll
                    for (int j = 0; j < 4; ++j) acc[i][j] = fmaf(a_[i], b_[j], acc[i][j]);
            }
            __syncthreads();
        }
    }
#pragma unroll
    for (int i = 0; i < 4; ++i) {
        int m = m0 + ty * 4 + i;
#pragma unroll
        for (int j = 0; j < 4; ++j) {
            int n = n0 + tx * 4 + j;
            if (n < p.N) {
                float v = acc[i][j];
                if (p.bias1) v += p.bias1[n];
                if (p.bias2) v += p.bias2[n];
                if (p.act) v = tanhf(v);
                p.C[(size_t)m * p.ldc + n] = v;
                if (p.C2) p.C2[(size_t)m * p.ldc2 + n] = v;
            }
        }
    }
}

// ---------------- fused LSTM pointwise (both paths), layer l ------------------
__global__ void k_lstm_pw(int layer) {
    int idx = blockIdx.x * 256 + threadIdx.x;
    if (idx < CB * HGD) {
        int b = idx / HGD, h = idx % HGD;
        const float* g = &g_buf[OFF_GG + (size_t)b * 4 * HGD];
        float iv = sigm(g[h]);
        float fv = sigm(g[HGD + h]);
        float gv = tanhf(g[2 * HGD + h]);
        float ov = sigm(g[3 * HGD + h]);
        size_t off = OFF_GC + (size_t)layer * CB * HGD + idx;
        float c = fv * g_buf[off] + iv * gv;
        g_buf[off] = c;
        g_buf[OFF_GH + (size_t)layer * CB * HGD + idx] = ov * tanhf(c);
    } else {
        int j = idx - CB * HGD;
        if (j >= CB * HWD) return;
        int b = j / HWD, h = j % HWD;
        const float* g = &g_buf[OFF_GW + (size_t)b * 4 * HWD];
        float iv = sigm(g[h]);
        float fv = sigm(g[HWD + h]);
        float gv = tanhf(g[2 * HWD + h]);
        float ov = sigm(g[3 * HWD + h]);
        size_t off = OFF_WC + (size_t)layer * CB * HWD + j;
        float c = fv * g_buf[off] + iv * gv;
        g_buf[off] = c;
        g_buf[OFF_WH + (size_t)layer * CB * HWD + j] = ov * tanhf(c);
    }
}

// ---------------- host: launch sequence ----------------
extern "C" void kernel_launch(void* const* d_in, const int* in_sizes, int n_in,
                              void* d_out, int out_size) {
    const float* ctx    = (const float*)d_in[0];
    const float* goal0  = (const float*)d_in[1];
    const float* w0     = (const float*)d_in[2];
    const float* bg_W   = (const float*)d_in[3];
    const float* bg_b   = (const float*)d_in[4];
    const float* bw_W   = (const float*)d_in[5];
    const float* bw_b   = (const float*)d_in[6];
    const float* fcg_W  = (const float*)d_in[7];
    const float* fcg_b  = (const float*)d_in[8];
    const float* fcw_W  = (const float*)d_in[9];
    const float* fcw_b  = (const float*)d_in[10];
    const float* lg_Wih = (const float*)d_in[11];
    const float* lg_Whh = (const float*)d_in[12];
    const float* lg_bih = (const float*)d_in[13];
    const float* lg_bhh = (const float*)d_in[14];
    const float* lw_Wih = (const float*)d_in[15];
    const float* lw_Whh = (const float*)d_in[16];
    const float* lw_bih = (const float*)d_in[17];
    const float* lw_bhh = (const float*)d_in[18];
    const float* og_W   = (const float*)d_in[19];
    const float* og_b   = (const float*)d_in[20];
    const float* ow_W   = (const float*)d_in[21];
    const float* ow_b   = (const float*)d_in[22];
    float* out = (float*)d_out;

    void* sym = nullptr;
    cudaGetSymbolAddress(&sym, g_buf);
    float* Gb = (float*)sym;
    float* P_XPRE = Gb + OFF_XPRE;
    float* P_YPRE = Gb + OFF_YPRE;
    float* P_X    = Gb + OFF_X;
    float* P_Y    = Gb + OFF_Y;
    float* P_GG   = Gb + OFF_GG;
    float* P_GW   = Gb + OFF_GW;
    float* P_GH   = Gb + OFF_GH;
    float* P_WH   = Gb + OFF_WH;
    float* P_PG   = Gb + OFF_PG;
    float* P_PW   = Gb + OFF_PW;

    // precompute (loop-invariant) + init
    k_transpose_ctx<<<512, 256>>>(ctx);
    k_tmpg<<<256, 256>>>(bg_W);
    k_tmpw<<<dim3(5, 4, 512), 256>>>(ctx, bw_W);
    k_init<<<1842, 256>>>(goal0, w0, out);

    for (int t = 1; t <= NSTEP; ++t) {
        // 1) bilinear: ypre (from tmp_w) + xpre (from tmp_g)
        k_bilinear<<<dim3(CB, 9), 256>>>(bg_b, bw_b);

        // 2) fc layers with tanh
        {
            Prob p0 = {P_XPRE, fcg_W, PGD, nullptr, nullptr, 0, fcg_b, nullptr,
                       P_X, PGD, nullptr, 0, CB, PGD, 1};
            Prob p1 = {P_YPRE, fcw_W, PWD, nullptr, nullptr, 0, fcw_b, nullptr,
                       P_Y, PWD, nullptr, 0, CB, PWD, 1};
            k_gemm_dual<<<dim3(8, 4, 2), 256>>>(p0, p1);
        }

        // 3) LSTM layer 0 gates, then pointwise
        {
            Prob p0 = {P_X, lg_Wih, HGD,
                       P_GH, lg_Whh, HGD,
                       lg_bih, lg_bhh,
                       P_GG, 4 * HGD, nullptr, 0, CB, 4 * HGD, 0};
            Prob p1 = {P_Y, lw_Wih, HWD,
                       P_WH, lw_Whh, HWD,
                       lw_bih, lw_bhh,
                       P_GW, 4 * HWD, nullptr, 0, CB, 4 * HWD, 0};
            k_gemm_dual<<<dim3(32, 4, 2), 256>>>(p0, p1);
        }
        k_lstm_pw<<<768, 256>>>(0);

        // 4) LSTM layer 1 gates, then pointwise
        {
            Prob p0 = {P_GH, lg_Wih + (size_t)4 * HGD * HGD, HGD,
                       P_GH + (size_t)CB * HGD, lg_Whh + (size_t)4 * HGD * HGD, HGD,
                       lg_bih + 4 * HGD, lg_bhh + 4 * HGD,
                       P_GG, 4 * HGD, nullptr, 0, CB, 4 * HGD, 0};
            Prob p1 = {P_WH, lw_Wih + (size_t)4 * HWD * HWD, HWD,
                       P_WH + (size_t)CB * HWD, lw_Whh + (size_t)4 * HWD * HWD, HWD,
                       lw_bih + 4 * HWD, lw_bhh + 4 * HWD,
                       P_GW, 4 * HWD, nullptr, 0, CB, 4 * HWD, 0};
            k_gemm_dual<<<dim3(32, 4, 2), 256>>>(p0, p1);
        }
        k_lstm_pw<<<768, 256>>>(1);

        // 5) output projections -> d_out slices (and next-step pg/pw)
        {
            Prob p0 = {P_GH + (size_t)CB * HGD, og_W, HGD,
                       nullptr, nullptr, 0, og_b, nullptr,
                       out + (size_t)t * DOF, 20 * DOF,
                       P_PG, DOF, CB, DOF, 0};
            Prob p1 = {P_WH + (size_t)CB * HWD, ow_W, HWD,
                       nullptr, nullptr, 0, ow_b, nullptr,
                       out + (size_t)CB * 20 * DOF + (size_t)t * WSZ, 20 * WSZ,
                       P_PW, WSZ, CB, WSZ, 0};
            k_gemm_dual<<<dim3(5, 4, 2), 256>>>(p0, p1);
        }
    }
}